// round 12
// baseline (speedup 1.0000x reference)
#include <cuda_runtime.h>
#include <cuda_bf16.h>
#include <math.h>
#include <stdint.h>

// ---------------- problem constants ----------------
#define TT     1024      // tokens
#define HH     2048      // hidden
#define EE     32        // routed experts
#define TOPK   6
#define NGROUP 8
#define TOPKG  3
#define EPG    (EE/NGROUP)   // 4 experts per group
#define IMOE   768
#define ISH    1536          // 2 * IMOE
#define CAPE   768           // per-expert capacity
#define RSCALE 16.0f

// ---------------- scratch (static device globals; no allocation) ----------------
__device__ float g_logits[(size_t)TT*EE];            // router logits [1024,32]
__device__ float g_gu   [(size_t)TT*TOPK * 2*IMOE];  // routed gate_up outputs  [6144,1536]
__device__ float g_h    [(size_t)TT*TOPK * IMOE];    // routed silu*up          [6144, 768]
__device__ float g_y    [(size_t)TT*TOPK * HH];      // routed expert outputs   [6144,2048]
__device__ float g_gu_sh[(size_t)TT * 2*ISH];        // shared gate_up          [1024,3072]
__device__ float g_h_sh [(size_t)TT * ISH];          // shared silu*up          [1024,1536]
__device__ float g_wcomb[TT*TOPK];                   // combine weights (0 if dropped)
__device__ int   g_slot_tok [EE*CAPE];               // token index per expert slot
__device__ int   g_slot_flat[EE*CAPE];               // flat (t*K+k) per expert slot
__device__ int   g_cnt[EE];                          // per-expert assignment count

// ---------------- init ----------------
__global__ void init_kernel() {
    if (threadIdx.x < EE) g_cnt[threadIdx.x] = 0;
}

// ---------------- router logits: one thread per (t,e), SEQUENTIAL ascending-k fp32 fma ----
// Bit-replicates the reference's per-output single-accumulator ascending-k chain.
// DO NOT TOUCH: this exact ordering is what makes routing decisions match.
__global__ void logits_kernel(const float* __restrict__ x,
                              const float* __restrict__ gate_w) {
    __shared__ float sx[4][HH];               // 4 tokens staged, 32KB
    const int t0 = blockIdx.x * 4;
    const int tid = threadIdx.x;              // 128 threads: 4 tokens x 32 experts
    for (int i = tid; i < 4*HH; i += 128)
        sx[i >> 11][i & (HH-1)] = x[(size_t)(t0 + (i >> 11)) * HH + (i & (HH-1))];
    __syncthreads();

    const int tl = tid & 3;
    const int e  = tid >> 2;
    const float* gw = gate_w + (size_t)e * HH;
    float acc = 0.f;
    #pragma unroll 8
    for (int k = 0; k < HH; ++k)
        acc = fmaf(sx[tl][k], gw[k], acc);    // single chain, ascending k
    g_logits[(size_t)(t0 + tl) * EE + e] = acc;
}

// ---------------- selection: fp32 softmax (jax form) + group-limited top-k + dispatch ----
__global__ void select_kernel() {
    const int t = blockIdx.x * blockDim.x + threadIdx.x;
    if (t >= TT) return;
    const float* l = g_logits + (size_t)t * EE;

    float mx = l[0];
    for (int e = 1; e < EE; ++e) mx = fmaxf(mx, l[e]);
    float ex[EE]; float sum = 0.f;
    for (int e = 0; e < EE; ++e) { ex[e] = expf(l[e] - mx); sum += ex[e]; }
    float sc[EE];
    for (int e = 0; e < EE; ++e) sc[e] = ex[e] / sum;

    float gs[NGROUP];
    for (int g = 0; g < NGROUP; ++g) {
        float m = sc[g * EPG];
        for (int j = 1; j < EPG; ++j) m = fmaxf(m, sc[g * EPG + j]);
        gs[g] = m;
    }
    bool gsel[NGROUP];
    for (int g = 0; g < NGROUP; ++g) gsel[g] = false;
    for (int r = 0; r < TOPKG; ++r) {
        int best = -1; float bv = -1e30f;
        for (int g = 0; g < NGROUP; ++g)
            if (!gsel[g] && gs[g] > bv) { bv = gs[g]; best = g; }
        gsel[best] = true;
    }
    float ms[EE];
    for (int e = 0; e < EE; ++e) ms[e] = gsel[e / EPG] ? sc[e] : 0.f;
    for (int k = 0; k < TOPK; ++k) {
        int best = 0; float bv = -1.f;
        for (int e = 0; e < EE; ++e)
            if (ms[e] > bv) { bv = ms[e]; best = e; }
        ms[best] = -1.f;
        const int flat = t * TOPK + k;
        const int pos = atomicAdd(&g_cnt[best], 1);
        if (pos < CAPE) {
            g_slot_tok [best * CAPE + pos] = t;
            g_slot_flat[best * CAPE + pos] = flat;
            g_wcomb[flat] = bv;
        } else {
            g_wcomb[flat] = 0.f;
        }
    }
}

// ================= TF32 tensor-core NT GEMM (exact R8 body — proven fastest) =================
// cp.async double-buffered, prefetch at loop top, wait_group 1; cvt.rna.tf32 at
// fragment load (cublas numerics), fp32 acc. 128x128x32 tile, 256 thr, m16n8k8.
#define BM 128
#define BN 128
#define BKK 32
#define SPAD 4
#define SROW (BKK + SPAD)          // 36 words; 144B row stride (16B-aligned)
#define STAGE_FLTS (BM * SROW)     // per-matrix per-stage floats (4608)
#define SMEM_FLTS  (4 * STAGE_FLTS) // A0,A1,B0,B1 = 73728B

__device__ __forceinline__ uint32_t tf32b(float x) {
    uint32_t u;
    asm("cvt.rna.tf32.f32 %0, %1;" : "=r"(u) : "f"(x));
    return u;
}

__device__ __forceinline__ void mma_tf32(float c[4], const uint32_t a[4], const uint32_t b[2]) {
    asm volatile(
        "mma.sync.aligned.m16n8k8.row.col.f32.tf32.tf32.f32 "
        "{%0,%1,%2,%3}, {%4,%5,%6,%7}, {%8,%9}, {%0,%1,%2,%3};\n"
        : "+f"(c[0]), "+f"(c[1]), "+f"(c[2]), "+f"(c[3])
        : "r"(a[0]), "r"(a[1]), "r"(a[2]), "r"(a[3]), "r"(b[0]), "r"(b[1]));
}

__device__ __forceinline__ void cp16(uint32_t smem_addr, const float* gptr, int srcsize) {
    asm volatile("cp.async.cg.shared.global [%0], [%1], 16, %2;\n"
                 :: "r"(smem_addr), "l"(gptr), "r"(srcsize));
}

__device__ __forceinline__ void gemm_tc_body(
    const float* __restrict__ A, int lda,
    const float* __restrict__ B,            // row-major [N, Klen]
    float* __restrict__ C, int ldc,
    const int* __restrict__ arow,           // nullable: A row = arow[m]
    const int* __restrict__ crow,           // nullable: C row = crow[m]
    int M, int Klen)
{
    const int m0 = blockIdx.y * BM;
    if (m0 >= M) return;
    const int n0 = blockIdx.x * BN;

    extern __shared__ float smem[];
    float* Asf = smem;                        // [2][BM][SROW]
    float* Bsf = smem + 2 * STAGE_FLTS;       // [2][BN][SROW]
    const uint32_t smem_base = (uint32_t)__cvta_generic_to_shared(smem);
    const uint32_t As_u = smem_base;
    const uint32_t Bs_u = smem_base + 2 * STAGE_FLTS * 4;

    const int tid  = threadIdx.x;
    const int warp = tid >> 5, lane = tid & 31;
    const int wm = (warp & 1) * 64;           // warp m-offset within block
    const int wn = (warp >> 1) * 32;          // warp n-offset within block
    const int gid = lane >> 2, tig = lane & 3;

    // global-load mapping: each thread cp.async's one float4 per pass; 4 passes/matrix
    const int lrow = tid >> 3;                // 0..31
    const int lcol = (tid & 7) * 4;           // 0,4,...,28

    // resolve gathered A rows once
    long long arows[4]; int asz[4];
    #pragma unroll
    for (int p = 0; p < 4; ++p) {
        const int m = m0 + lrow + p * 32;
        const bool ok = m < M;
        asz[p] = ok ? 16 : 0;                 // cp.async src-size 0 => zero-fill
        arows[p] = ok ? (arow ? arow[m] : m) : 0;
    }
    const long long brow = (long long)(n0 + lrow) * Klen;

    float acc[4][4][4];
    #pragma unroll
    for (int i = 0; i < 4; ++i)
        #pragma unroll
        for (int j = 0; j < 4; ++j)
            #pragma unroll
            for (int r = 0; r < 4; ++r) acc[i][j][r] = 0.f;

    auto prefetch = [&](int st, int k0) {
        const uint32_t abase = As_u + (uint32_t)(st * STAGE_FLTS) * 4;
        const uint32_t bbase = Bs_u + (uint32_t)(st * STAGE_FLTS) * 4;
        #pragma unroll
        for (int p = 0; p < 4; ++p) {
            const int r = lrow + p * 32;
            cp16(abase + (uint32_t)(r * SROW + lcol) * 4,
                 A + arows[p] * (long long)lda + k0 + lcol, asz[p]);
            cp16(bbase + (uint32_t)(r * SROW + lcol) * 4,
                 B + brow + (long long)p * 32 * Klen + k0 + lcol, 16);
        }
        asm volatile("cp.async.commit_group;\n");
    };

    prefetch(0, 0);

    int s = 0;
    for (int k0 = 0; k0 < Klen; k0 += BKK, s ^= 1) {
        const bool has_next = (k0 + BKK) < Klen;
        if (has_next) prefetch(s ^ 1, k0 + BKK);
        if (has_next) asm volatile("cp.async.wait_group 1;\n");
        else          asm volatile("cp.async.wait_group 0;\n");
        __syncthreads();

        const float* As = Asf + s * STAGE_FLTS;
        const float* Bs = Bsf + s * STAGE_FLTS;
        #pragma unroll
        for (int kk = 0; kk < BKK; kk += 8) {
            uint32_t af[4][4], bf[4][2];
            #pragma unroll
            for (int mt = 0; mt < 4; ++mt) {
                const int r = wm + mt * 16 + gid;
                af[mt][0] = tf32b(As[ r      * SROW + kk + tig    ]);
                af[mt][1] = tf32b(As[(r + 8) * SROW + kk + tig    ]);
                af[mt][2] = tf32b(As[ r      * SROW + kk + tig + 4]);
                af[mt][3] = tf32b(As[(r + 8) * SROW + kk + tig + 4]);
            }
            #pragma unroll
            for (int nt = 0; nt < 4; ++nt) {
                const int r = wn + nt * 8 + gid;
                bf[nt][0] = tf32b(Bs[r * SROW + kk + tig    ]);
                bf[nt][1] = tf32b(Bs[r * SROW + kk + tig + 4]);
            }
            #pragma unroll
            for (int mt = 0; mt < 4; ++mt)
                #pragma unroll
                for (int nt = 0; nt < 4; ++nt)
                    mma_tf32(acc[mt][nt], af[mt], bf[nt]);
        }
        __syncthreads();
    }

    // epilogue: c0,c1 at (gid, 2*tig), c2,c3 at (gid+8, 2*tig)
    #pragma unroll
    for (int mt = 0; mt < 4; ++mt) {
        const int ma = m0 + wm + mt * 16 + gid;
        const int mb = ma + 8;
        #pragma unroll
        for (int nt = 0; nt < 4; ++nt) {
            const int col = n0 + wn + nt * 8 + 2 * tig;
            if (ma < M) {
                const long long r = crow ? crow[ma] : ma;
                *(float2*)(C + r * (long long)ldc + col) = make_float2(acc[mt][nt][0], acc[mt][nt][1]);
            }
            if (mb < M) {
                const long long r = crow ? crow[mb] : mb;
                *(float2*)(C + r * (long long)ldc + col) = make_float2(acc[mt][nt][2], acc[mt][nt][3]);
            }
        }
    }
}

// ---- GEMM wrappers (blockIdx.z = expert where applicable) ----
__global__ void __launch_bounds__(256, 2) gemm_routed1(const float* __restrict__ x, const float* __restrict__ w13) {
    const int e = blockIdx.z;
    const int M = min(g_cnt[e], CAPE);
    gemm_tc_body(x, HH,
                 w13 + (long long)e * (2*IMOE) * HH,
                 g_gu, 2*IMOE,
                 g_slot_tok + e*CAPE, g_slot_flat + e*CAPE,
                 M, HH);
}
__global__ void __launch_bounds__(256, 2) gemm_routed2(const float* __restrict__ w2) {
    const int e = blockIdx.z;
    const int M = min(g_cnt[e], CAPE);
    gemm_tc_body(g_h, IMOE,
                 w2 + (long long)e * HH * IMOE,
                 g_y, HH,
                 g_slot_flat + e*CAPE, g_slot_flat + e*CAPE,
                 M, IMOE);
}
__global__ void __launch_bounds__(256, 2) gemm_shared1(const float* __restrict__ x, const float* __restrict__ sgu) {
    gemm_tc_body(x, HH, sgu, g_gu_sh, 2*ISH, nullptr, nullptr, TT, HH);
}
__global__ void __launch_bounds__(256, 2) gemm_shared2(const float* __restrict__ sdn, float* __restrict__ out) {
    gemm_tc_body(g_h_sh, ISH, sdn, out, HH, nullptr, nullptr, TT, ISH);
}

// ---------------- SwiGLU elementwise (exact fp32) ----------------
__global__ void swiglu_routed() {
    const int slot = blockIdx.x;                 // e*CAPE + pos
    const int e = slot / CAPE, pos = slot % CAPE;
    if (pos >= g_cnt[e]) return;
    const int flat = g_slot_flat[slot];
    const float* gu = g_gu + (long long)flat * (2*IMOE);
    float* h = g_h + (long long)flat * IMOE;
    for (int i = threadIdx.x; i < IMOE; i += blockDim.x) {
        float g = gu[i], u = gu[i + IMOE];
        h[i] = u * g / (1.f + expf(-g));
    }
}
__global__ void swiglu_shared() {
    const int t = blockIdx.x;
    const float* gu = g_gu_sh + (long long)t * (2*ISH);
    float* h = g_h_sh + (long long)t * ISH;
    for (int i = threadIdx.x; i < ISH; i += blockDim.x) {
        float g = gu[i], u = gu[i + ISH];
        h[i] = u * g / (1.f + expf(-g));
    }
}

// ---------------- combine: out += SCALE * sum_k w_k * y_k ----------------
__global__ void combine_kernel(float* __restrict__ out) {
    const int t = blockIdx.x;
    const int base = t * TOPK;
    float w[TOPK];
    #pragma unroll
    for (int k = 0; k < TOPK; ++k) w[k] = g_wcomb[base + k];
    float* orow = out + (long long)t * HH;
    for (int h = threadIdx.x; h < HH; h += blockDim.x) {
        float r = 0.f;
        #pragma unroll
        for (int k = 0; k < TOPK; ++k)
            r += w[k] * g_y[(long long)(base + k) * HH + h];
        orow[h] += RSCALE * r;
    }
}

// ---------------- launch: fork-join graph (routed path ∥ shared path) ----------------
extern "C" void kernel_launch(void* const* d_in, const int* in_sizes, int n_in,
                              void* d_out, int out_size) {
    const float* x     = (const float*)d_in[0];   // [T,H]
    const float* gatew = (const float*)d_in[1];   // [E,H]
    const float* w13   = (const float*)d_in[2];   // [E,2I,H]
    const float* w2    = (const float*)d_in[3];   // [E,H,I]
    const float* sgu   = (const float*)d_in[4];   // [2*ISH,H]
    const float* sdn   = (const float*)d_in[5];   // [H,ISH]
    float* out = (float*)d_out;                   // [T,H]

    const int smem_bytes = SMEM_FLTS * 4;         // 73728

    static cudaStream_t s1 = nullptr;
    static cudaEvent_t evFork = nullptr, evJoin = nullptr;
    static bool init_done = false;
    if (!init_done) {
        cudaFuncSetAttribute(gemm_routed1, cudaFuncAttributeMaxDynamicSharedMemorySize, smem_bytes);
        cudaFuncSetAttribute(gemm_routed2, cudaFuncAttributeMaxDynamicSharedMemorySize, smem_bytes);
        cudaFuncSetAttribute(gemm_shared1, cudaFuncAttributeMaxDynamicSharedMemorySize, smem_bytes);
        cudaFuncSetAttribute(gemm_shared2, cudaFuncAttributeMaxDynamicSharedMemorySize, smem_bytes);
        cudaStreamCreateWithFlags(&s1, cudaStreamNonBlocking);
        cudaEventCreateWithFlags(&evFork, cudaEventDisableTiming);
        cudaEventCreateWithFlags(&evJoin, cudaEventDisableTiming);
        init_done = true;
    }

    // ---- fork: shared-expert path depends only on x ----
    cudaEventRecord(evFork, 0);
    cudaStreamWaitEvent(s1, evFork, 0);

    // shared path on s1 (writes d_out fully via shared2)
    {
        dim3 g((2*ISH)/BN, TT/BM, 1);             // (24,8)
        gemm_shared1<<<g, 256, smem_bytes, s1>>>(x, sgu);
    }
    swiglu_shared<<<TT, 256, 0, s1>>>();
    {
        dim3 g(HH/BN, TT/BM, 1);                  // (16,8)
        gemm_shared2<<<g, 256, smem_bytes, s1>>>(sdn, out);
    }
    cudaEventRecord(evJoin, s1);

    // routed path on origin stream
    init_kernel<<<1, 32>>>();
    logits_kernel<<<TT/4, 128>>>(x, gatew);
    select_kernel<<<4, 256>>>();
    {
        dim3 g((2*IMOE)/BN, CAPE/BM, EE);         // (12,6,32)
        gemm_routed1<<<g, 256, smem_bytes>>>(x, w13);
    }
    swiglu_routed<<<EE*CAPE, 256>>>();
    {
        dim3 g(HH/BN, CAPE/BM, EE);               // (16,6,32)
        gemm_routed2<<<g, 256, smem_bytes>>>(w2);
    }

    // ---- join: combine needs g_y (origin) AND out from shared2 (s1) ----
    cudaStreamWaitEvent(0, evJoin, 0);
    combine_kernel<<<TT, 256>>>(out);
}

// round 14
// speedup vs baseline: 1.1602x; 1.1602x over previous
#include <cuda_runtime.h>
#include <cuda_bf16.h>
#include <math.h>
#include <stdint.h>

// ---------------- problem constants ----------------
#define TT     1024      // tokens
#define HH     2048      // hidden
#define EE     32        // routed experts
#define TOPK   6
#define NGROUP 8
#define TOPKG  3
#define EPG    (EE/NGROUP)   // 4 experts per group
#define IMOE   768
#define ISH    1536          // 2 * IMOE
#define CAPE   768           // per-expert capacity
#define RSCALE 16.0f

// ---------------- scratch (static device globals; no allocation) ----------------
__device__ float g_logits[(size_t)TT*EE];            // router logits [1024,32]
__device__ float g_gu   [(size_t)TT*TOPK * 2*IMOE];  // routed gate_up outputs  [6144,1536]
__device__ float g_h    [(size_t)TT*TOPK * IMOE];    // routed silu*up          [6144, 768]
__device__ float g_y    [(size_t)TT*TOPK * HH];      // routed expert outputs   [6144,2048]
__device__ float g_gu_sh[(size_t)TT * 2*ISH];        // shared gate_up          [1024,3072]
__device__ float g_h_sh [(size_t)TT * ISH];          // shared silu*up          [1024,1536]
__device__ float g_wcomb[TT*TOPK];                   // combine weights (0 if dropped)
__device__ int   g_slot_tok [EE*CAPE];               // token index per expert slot
__device__ int   g_slot_flat[EE*CAPE];               // flat (t*K+k) per expert slot
__device__ int   g_cnt[EE];                          // per-expert assignment count

// ---------------- init ----------------
__global__ void init_kernel() {
    if (threadIdx.x < EE) g_cnt[threadIdx.x] = 0;
}

// ---------------- router logits: one thread per (t,e), SEQUENTIAL ascending-k fp32 fma ----
// Bit-replicates the reference's per-output single-accumulator ascending-k chain.
// DO NOT TOUCH: this exact ordering is what makes routing decisions match.
__global__ void logits_kernel(const float* __restrict__ x,
                              const float* __restrict__ gate_w) {
    __shared__ float sx[4][HH];               // 4 tokens staged, 32KB
    const int t0 = blockIdx.x * 4;
    const int tid = threadIdx.x;              // 128 threads: 4 tokens x 32 experts
    for (int i = tid; i < 4*HH; i += 128)
        sx[i >> 11][i & (HH-1)] = x[(size_t)(t0 + (i >> 11)) * HH + (i & (HH-1))];
    __syncthreads();

    const int tl = tid & 3;
    const int e  = tid >> 2;
    const float* gw = gate_w + (size_t)e * HH;
    float acc = 0.f;
    #pragma unroll 8
    for (int k = 0; k < HH; ++k)
        acc = fmaf(sx[tl][k], gw[k], acc);    // single chain, ascending k
    g_logits[(size_t)(t0 + tl) * EE + e] = acc;
}

// ---------------- selection: fp32 softmax (jax form) + group-limited top-k + dispatch ----
__global__ void select_kernel() {
    const int t = blockIdx.x * blockDim.x + threadIdx.x;
    if (t >= TT) return;
    const float* l = g_logits + (size_t)t * EE;

    float mx = l[0];
    for (int e = 1; e < EE; ++e) mx = fmaxf(mx, l[e]);
    float ex[EE]; float sum = 0.f;
    for (int e = 0; e < EE; ++e) { ex[e] = expf(l[e] - mx); sum += ex[e]; }
    float sc[EE];
    for (int e = 0; e < EE; ++e) sc[e] = ex[e] / sum;

    float gs[NGROUP];
    for (int g = 0; g < NGROUP; ++g) {
        float m = sc[g * EPG];
        for (int j = 1; j < EPG; ++j) m = fmaxf(m, sc[g * EPG + j]);
        gs[g] = m;
    }
    bool gsel[NGROUP];
    for (int g = 0; g < NGROUP; ++g) gsel[g] = false;
    for (int r = 0; r < TOPKG; ++r) {
        int best = -1; float bv = -1e30f;
        for (int g = 0; g < NGROUP; ++g)
            if (!gsel[g] && gs[g] > bv) { bv = gs[g]; best = g; }
        gsel[best] = true;
    }
    float ms[EE];
    for (int e = 0; e < EE; ++e) ms[e] = gsel[e / EPG] ? sc[e] : 0.f;
    for (int k = 0; k < TOPK; ++k) {
        int best = 0; float bv = -1.f;
        for (int e = 0; e < EE; ++e)
            if (ms[e] > bv) { bv = ms[e]; best = e; }
        ms[best] = -1.f;
        const int flat = t * TOPK + k;
        const int pos = atomicAdd(&g_cnt[best], 1);
        if (pos < CAPE) {
            g_slot_tok [best * CAPE + pos] = t;
            g_slot_flat[best * CAPE + pos] = flat;
            g_wcomb[flat] = bv;
        } else {
            g_wcomb[flat] = 0.f;
        }
    }
}

// ================= TF32 tensor-core NT GEMM (exact R8 body — proven fastest) =================
// cp.async double-buffered, prefetch at loop top, wait_group 1; cvt.rna.tf32 at
// fragment load (cublas numerics), fp32 acc. 128x128x32 tile, 256 thr, m16n8k8.
#define BM 128
#define BN 128
#define BKK 32
#define SPAD 4
#define SROW (BKK + SPAD)          // 36 words; 144B row stride (16B-aligned)
#define STAGE_FLTS (BM * SROW)     // per-matrix per-stage floats (4608)
#define SMEM_FLTS  (4 * STAGE_FLTS) // A0,A1,B0,B1 = 73728B

__device__ __forceinline__ uint32_t tf32b(float x) {
    uint32_t u;
    asm("cvt.rna.tf32.f32 %0, %1;" : "=r"(u) : "f"(x));
    return u;
}

__device__ __forceinline__ void mma_tf32(float c[4], const uint32_t a[4], const uint32_t b[2]) {
    asm volatile(
        "mma.sync.aligned.m16n8k8.row.col.f32.tf32.tf32.f32 "
        "{%0,%1,%2,%3}, {%4,%5,%6,%7}, {%8,%9}, {%0,%1,%2,%3};\n"
        : "+f"(c[0]), "+f"(c[1]), "+f"(c[2]), "+f"(c[3])
        : "r"(a[0]), "r"(a[1]), "r"(a[2]), "r"(a[3]), "r"(b[0]), "r"(b[1]));
}

__device__ __forceinline__ void cp16(uint32_t smem_addr, const float* gptr, int srcsize) {
    asm volatile("cp.async.cg.shared.global [%0], [%1], 16, %2;\n"
                 :: "r"(smem_addr), "l"(gptr), "r"(srcsize));
}

// bx, by = tile coordinates (replaces blockIdx.x/y so callers can fuse grids)
__device__ __forceinline__ void gemm_tc_body(
    int bx, int by,
    const float* __restrict__ A, int lda,
    const float* __restrict__ B,            // row-major [N, Klen]
    float* __restrict__ C, int ldc,
    const int* __restrict__ arow,           // nullable: A row = arow[m]
    const int* __restrict__ crow,           // nullable: C row = crow[m]
    int M, int Klen)
{
    const int m0 = by * BM;
    if (m0 >= M) return;
    const int n0 = bx * BN;

    extern __shared__ float smem[];
    float* Asf = smem;                        // [2][BM][SROW]
    float* Bsf = smem + 2 * STAGE_FLTS;       // [2][BN][SROW]
    const uint32_t smem_base = (uint32_t)__cvta_generic_to_shared(smem);
    const uint32_t As_u = smem_base;
    const uint32_t Bs_u = smem_base + 2 * STAGE_FLTS * 4;

    const int tid  = threadIdx.x;
    const int warp = tid >> 5, lane = tid & 31;
    const int wm = (warp & 1) * 64;           // warp m-offset within block
    const int wn = (warp >> 1) * 32;          // warp n-offset within block
    const int gid = lane >> 2, tig = lane & 3;

    // global-load mapping: each thread cp.async's one float4 per pass; 4 passes/matrix
    const int lrow = tid >> 3;                // 0..31
    const int lcol = (tid & 7) * 4;           // 0,4,...,28

    // resolve gathered A rows once
    long long arows[4]; int asz[4];
    #pragma unroll
    for (int p = 0; p < 4; ++p) {
        const int m = m0 + lrow + p * 32;
        const bool ok = m < M;
        asz[p] = ok ? 16 : 0;                 // cp.async src-size 0 => zero-fill
        arows[p] = ok ? (arow ? arow[m] : m) : 0;
    }
    const long long brow = (long long)(n0 + lrow) * Klen;

    float acc[4][4][4];
    #pragma unroll
    for (int i = 0; i < 4; ++i)
        #pragma unroll
        for (int j = 0; j < 4; ++j)
            #pragma unroll
            for (int r = 0; r < 4; ++r) acc[i][j][r] = 0.f;

    auto prefetch = [&](int st, int k0) {
        const uint32_t abase = As_u + (uint32_t)(st * STAGE_FLTS) * 4;
        const uint32_t bbase = Bs_u + (uint32_t)(st * STAGE_FLTS) * 4;
        #pragma unroll
        for (int p = 0; p < 4; ++p) {
            const int r = lrow + p * 32;
            cp16(abase + (uint32_t)(r * SROW + lcol) * 4,
                 A + arows[p] * (long long)lda + k0 + lcol, asz[p]);
            cp16(bbase + (uint32_t)(r * SROW + lcol) * 4,
                 B + brow + (long long)p * 32 * Klen + k0 + lcol, 16);
        }
        asm volatile("cp.async.commit_group;\n");
    };

    prefetch(0, 0);

    int s = 0;
    for (int k0 = 0; k0 < Klen; k0 += BKK, s ^= 1) {
        const bool has_next = (k0 + BKK) < Klen;
        if (has_next) prefetch(s ^ 1, k0 + BKK);
        if (has_next) asm volatile("cp.async.wait_group 1;\n");
        else          asm volatile("cp.async.wait_group 0;\n");
        __syncthreads();

        const float* As = Asf + s * STAGE_FLTS;
        const float* Bs = Bsf + s * STAGE_FLTS;
        #pragma unroll
        for (int kk = 0; kk < BKK; kk += 8) {
            uint32_t af[4][4], bf[4][2];
            #pragma unroll
            for (int mt = 0; mt < 4; ++mt) {
                const int r = wm + mt * 16 + gid;
                af[mt][0] = tf32b(As[ r      * SROW + kk + tig    ]);
                af[mt][1] = tf32b(As[(r + 8) * SROW + kk + tig    ]);
                af[mt][2] = tf32b(As[ r      * SROW + kk + tig + 4]);
                af[mt][3] = tf32b(As[(r + 8) * SROW + kk + tig + 4]);
            }
            #pragma unroll
            for (int nt = 0; nt < 4; ++nt) {
                const int r = wn + nt * 8 + gid;
                bf[nt][0] = tf32b(Bs[r * SROW + kk + tig    ]);
                bf[nt][1] = tf32b(Bs[r * SROW + kk + tig + 4]);
            }
            #pragma unroll
            for (int mt = 0; mt < 4; ++mt)
                #pragma unroll
                for (int nt = 0; nt < 4; ++nt)
                    mma_tf32(acc[mt][nt], af[mt], bf[nt]);
        }
        __syncthreads();
    }

    // epilogue: c0,c1 at (gid, 2*tig), c2,c3 at (gid+8, 2*tig)
    #pragma unroll
    for (int mt = 0; mt < 4; ++mt) {
        const int ma = m0 + wm + mt * 16 + gid;
        const int mb = ma + 8;
        #pragma unroll
        for (int nt = 0; nt < 4; ++nt) {
            const int col = n0 + wn + nt * 8 + 2 * tig;
            if (ma < M) {
                const long long r = crow ? crow[ma] : ma;
                *(float2*)(C + r * (long long)ldc + col) = make_float2(acc[mt][nt][0], acc[mt][nt][1]);
            }
            if (mb < M) {
                const long long r = crow ? crow[mb] : mb;
                *(float2*)(C + r * (long long)ldc + col) = make_float2(acc[mt][nt][2], acc[mt][nt][3]);
            }
        }
    }
}

// ---- fused GEMM stage 1: routed gate_up (blocks 0..2303) + shared gate_up (2304..2495) ----
#define R1_BLOCKS (12 * 6 * EE)              // 2304
#define S1_BLOCKS (24 * 8)                   // 192
__global__ void __launch_bounds__(256, 2) gemm_stage1(const float* __restrict__ x,
                                                      const float* __restrict__ w13,
                                                      const float* __restrict__ sgu) {
    const int bid = blockIdx.x;
    if (bid < R1_BLOCKS) {
        const int e   = bid / 72;             // 72 = 12*6 tiles per expert
        const int rem = bid % 72;
        const int by  = rem / 12, bx = rem % 12;
        const int M = min(g_cnt[e], CAPE);
        gemm_tc_body(bx, by, x, HH,
                     w13 + (long long)e * (2*IMOE) * HH,
                     g_gu, 2*IMOE,
                     g_slot_tok + e*CAPE, g_slot_flat + e*CAPE,
                     M, HH);
    } else {
        const int sid = bid - R1_BLOCKS;
        const int by = sid / 24, bx = sid % 24;
        gemm_tc_body(bx, by, x, HH, sgu, g_gu_sh, 2*ISH, nullptr, nullptr, TT, HH);
    }
}

// ---- fused GEMM stage 2: routed down (blocks 0..3071) + shared down (3072..3199) ----
#define R2_BLOCKS (16 * 6 * EE)              // 3072
#define S2_BLOCKS (16 * 8)                   // 128
__global__ void __launch_bounds__(256, 2) gemm_stage2(const float* __restrict__ w2,
                                                      const float* __restrict__ sdn,
                                                      float* __restrict__ out) {
    const int bid = blockIdx.x;
    if (bid < R2_BLOCKS) {
        const int e   = bid / 96;             // 96 = 16*6 tiles per expert
        const int rem = bid % 96;
        const int by  = rem / 16, bx = rem % 16;
        const int M = min(g_cnt[e], CAPE);
        gemm_tc_body(bx, by, g_h, IMOE,
                     w2 + (long long)e * HH * IMOE,
                     g_y, HH,
                     g_slot_flat + e*CAPE, g_slot_flat + e*CAPE,
                     M, IMOE);
    } else {
        const int sid = bid - R2_BLOCKS;
        const int by = sid / 16, bx = sid % 16;
        gemm_tc_body(bx, by, g_h_sh, ISH, sdn, out, HH, nullptr, nullptr, TT, ISH);
    }
}

// ---------------- fused SwiGLU elementwise (exact fp32) ----------------
__global__ void swiglu_fused() {
    const int bid = blockIdx.x;
    if (bid < EE * CAPE) {
        const int e = bid / CAPE, pos = bid % CAPE;
        if (pos >= g_cnt[e]) return;
        const int flat = g_slot_flat[bid];
        const float* gu = g_gu + (long long)flat * (2*IMOE);
        float* h = g_h + (long long)flat * IMOE;
        for (int i = threadIdx.x; i < IMOE; i += blockDim.x) {
            float g = gu[i], u = gu[i + IMOE];
            h[i] = u * g / (1.f + expf(-g));
        }
    } else {
        const int t = bid - EE * CAPE;
        const float* gu = g_gu_sh + (long long)t * (2*ISH);
        float* h = g_h_sh + (long long)t * ISH;
        for (int i = threadIdx.x; i < ISH; i += blockDim.x) {
            float g = gu[i], u = gu[i + ISH];
            h[i] = u * g / (1.f + expf(-g));
        }
    }
}

// ---------------- combine: out += SCALE * sum_k w_k * y_k ----------------
__global__ void combine_kernel(float* __restrict__ out) {
    const int t = blockIdx.x;
    const int base = t * TOPK;
    float w[TOPK];
    #pragma unroll
    for (int k = 0; k < TOPK; ++k) w[k] = g_wcomb[base + k];
    float* orow = out + (long long)t * HH;
    for (int h = threadIdx.x; h < HH; h += blockDim.x) {
        float r = 0.f;
        #pragma unroll
        for (int k = 0; k < TOPK; ++k)
            r += w[k] * g_y[(long long)(base + k) * HH + h];
        orow[h] += RSCALE * r;
    }
}

// ---------------- launch ----------------
extern "C" void kernel_launch(void* const* d_in, const int* in_sizes, int n_in,
                              void* d_out, int out_size) {
    const float* x     = (const float*)d_in[0];   // [T,H]
    const float* gatew = (const float*)d_in[1];   // [E,H]
    const float* w13   = (const float*)d_in[2];   // [E,2I,H]
    const float* w2    = (const float*)d_in[3];   // [E,H,I]
    const float* sgu   = (const float*)d_in[4];   // [2*ISH,H]
    const float* sdn   = (const float*)d_in[5];   // [H,ISH]
    float* out = (float*)d_out;                   // [T,H]

    const int smem_bytes = SMEM_FLTS * 4;         // 73728
    static bool attr_set = false;
    if (!attr_set) {
        cudaFuncSetAttribute(gemm_stage1, cudaFuncAttributeMaxDynamicSharedMemorySize, smem_bytes);
        cudaFuncSetAttribute(gemm_stage2, cudaFuncAttributeMaxDynamicSharedMemorySize, smem_bytes);
        attr_set = true;
    }

    init_kernel<<<1, 32>>>();
    logits_kernel<<<TT/4, 128>>>(x, gatew);
    select_kernel<<<4, 256>>>();

    // stage 1: routed gate_up + shared gate_up in ONE grid (tail-filling)
    gemm_stage1<<<R1_BLOCKS + S1_BLOCKS, 256, smem_bytes>>>(x, w13, sgu);

    // fused swiglu (routed slots + shared tokens)
    swiglu_fused<<<EE*CAPE + TT, 256>>>();

    // stage 2: routed down + shared down in ONE grid (shared2 writes out fully)
    gemm_stage2<<<R2_BLOCKS + S2_BLOCKS, 256, smem_bytes>>>(w2, sdn, out);

    // combine routed into out
    combine_kernel<<<TT, 256>>>(out);
}